// round 6
// baseline (speedup 1.0000x reference)
#include <cuda_runtime.h>
#include <math.h>
#include <stdint.h>

#define NNODES 50000
#define EEDGES 800000
#define ETOT   (EEDGES + NNODES)
#define DHID   128
#define DFEAT  256          // HEADS * HID
#define NEG_SLOPE 0.2f
#define EPSV 1e-16f

// ---------------- scratch (no allocation allowed; zero-initialized at load) ----------------
__device__ float g_h1[NNODES * DFEAT];
__device__ float g_agg1[NNODES * DFEAT];
__device__ float g_h2[NNODES * DFEAT];
__device__ float g_agg2[NNODES * DFEAT];
__device__ float g_as[NNODES * 2];
__device__ float g_ad[NNODES * 2];
__device__ float g_wc[DFEAT + 1];
__device__ int   g_cnt[NNODES];      // stays zero between launches (scan_final re-zeroes)
__device__ int   g_rowptr[NNODES];
__device__ int   g_cursor[NNODES];   // after scatter: row end pointer (= rowptr + deg)
__device__ int   g_colidx[ETOT];
__device__ int   g_bsum[256];

// ================= CSR construction =================
__global__ void count_kernel(const int* __restrict__ ei, int* __restrict__ cnt,
                             int E, int Etot) {
    int t = blockIdx.x * blockDim.x + threadIdx.x;
    if (t >= Etot) return;
    int d = (t < E) ? ei[E + t] : (t - E);
    atomicAdd(&cnt[d], 1);
}

__global__ void scan_block_sums(const int* __restrict__ cnt, int* __restrict__ bsum, int N) {
    __shared__ int sh[256];
    int tid = threadIdx.x;
    int i = blockIdx.x * 256 + tid;
    sh[tid] = (i < N) ? cnt[i] : 0;
    __syncthreads();
    for (int s = 128; s > 0; s >>= 1) {
        if (tid < s) sh[tid] += sh[tid + s];
        __syncthreads();
    }
    if (tid == 0) bsum[blockIdx.x] = sh[0];
}

__global__ void scan_bsums(int* bsum, int nb) {
    __shared__ int sh[256];
    int tid = threadIdx.x;
    int v0 = (tid < nb) ? bsum[tid] : 0;
    sh[tid] = v0;
    __syncthreads();
    for (int off = 1; off < 256; off <<= 1) {
        int v = (tid >= off) ? sh[tid - off] : 0;
        __syncthreads();
        sh[tid] += v;
        __syncthreads();
    }
    if (tid < nb) bsum[tid] = sh[tid] - v0;   // exclusive
}

// also re-zeroes cnt so the next graph replay starts clean (no zero kernel needed)
__global__ void scan_final(int* __restrict__ cnt, const int* __restrict__ bsum,
                           int* __restrict__ rowptr, int* __restrict__ cursor, int N) {
    __shared__ int sh[256];
    int tid = threadIdx.x;
    int i = blockIdx.x * 256 + tid;
    int v0 = (i < N) ? cnt[i] : 0;
    sh[tid] = v0;
    __syncthreads();
    for (int off = 1; off < 256; off <<= 1) {
        int v = (tid >= off) ? sh[tid - off] : 0;
        __syncthreads();
        sh[tid] += v;
        __syncthreads();
    }
    if (i < N) {
        int excl = sh[tid] - v0 + bsum[blockIdx.x];
        rowptr[i] = excl;
        cursor[i] = excl;
        cnt[i] = 0;
    }
}

__global__ void scatter_kernel(const int* __restrict__ ei, int* __restrict__ cursor,
                               int* __restrict__ colidx, int E, int Etot) {
    int t = blockIdx.x * blockDim.x + threadIdx.x;
    if (t >= Etot) return;
    int s, d;
    if (t < E) { s = ei[t]; d = ei[E + t]; } else { s = d = t - E; }
    int pos = atomicAdd(&cursor[d], 1);
    colidx[pos] = s;
}

// ================= 3xTF32 tensor-core GEMM (R2 config — register budget sacred) =================
__device__ __forceinline__ uint32_t f2tf32(float f) {
    uint32_t u;
    asm("cvt.rna.tf32.f32 %0, %1;" : "=r"(u) : "f"(f));
    return u;
}

__device__ __forceinline__ void mma_tf32(float* c, const uint32_t* a, const uint32_t* b) {
    asm volatile(
        "mma.sync.aligned.m16n8k8.row.col.f32.tf32.tf32.f32 "
        "{%0,%1,%2,%3}, {%4,%5,%6,%7}, {%8,%9}, {%0,%1,%2,%3};"
        : "+f"(c[0]), "+f"(c[1]), "+f"(c[2]), "+f"(c[3])
        : "r"(a[0]), "r"(a[1]), "r"(a[2]), "r"(a[3]), "r"(b[0]), "r"(b[1]));
}

template <int FUSE_RELU>
__global__ void __launch_bounds__(256) gemm_tf32_kernel(
    const float* __restrict__ A, const float* __restrict__ B,
    const float* __restrict__ bias, float* __restrict__ C,
    int M, int N, int K)
{
    __shared__ uint32_t Ah[128][20];   // pad 4: frag bank = 4*gid+tig (bijective)
    __shared__ uint32_t Al[128][20];
    __shared__ uint32_t Bh[16][72];    // pad 8: frag bank = 8*tig+gid (bijective)
    __shared__ uint32_t Bl[16][72];

    const int tid  = threadIdx.x;
    const int lane = tid & 31;
    const int warp = tid >> 5;
    const int wm   = warp & 3;     // m warp: wm*32
    const int wn   = warp >> 2;    // n warp: wn*32
    const int gid  = lane >> 2;
    const int tig  = lane & 3;
    const int m0 = blockIdx.x * 128;
    const int n0 = blockIdx.y * 64;

    float c_[2][4][4];
#pragma unroll
    for (int fm = 0; fm < 2; fm++)
#pragma unroll
        for (int fn = 0; fn < 4; fn++)
#pragma unroll
            for (int j = 0; j < 4; j++) c_[fm][fn][j] = 0.f;

    for (int k0 = 0; k0 < K; k0 += 16) {
        // ---- load A tile (128x16): 512 float4, 2 per thread ----
#pragma unroll
        for (int it = 0; it < 2; it++) {
            int idx = tid + it * 256;
            int row = idx >> 2, c4 = idx & 3;
            int gm = m0 + row;
            float4 f = make_float4(0.f, 0.f, 0.f, 0.f);
            if (gm < M) f = *(const float4*)&A[(size_t)gm * K + k0 + c4 * 4];
            if (FUSE_RELU) {
                float4 bb = *(const float4*)&bias[k0 + c4 * 4];
                f.x = fmaxf(f.x + bb.x, 0.f);
                f.y = fmaxf(f.y + bb.y, 0.f);
                f.z = fmaxf(f.z + bb.z, 0.f);
                f.w = fmaxf(f.w + bb.w, 0.f);
            }
            uint32_t h0 = f2tf32(f.x), h1 = f2tf32(f.y), h2 = f2tf32(f.z), h3 = f2tf32(f.w);
            uint32_t l0 = f2tf32(f.x - __uint_as_float(h0));
            uint32_t l1 = f2tf32(f.y - __uint_as_float(h1));
            uint32_t l2 = f2tf32(f.z - __uint_as_float(h2));
            uint32_t l3 = f2tf32(f.w - __uint_as_float(h3));
            *(uint4*)&Ah[row][c4 * 4] = make_uint4(h0, h1, h2, h3);
            *(uint4*)&Al[row][c4 * 4] = make_uint4(l0, l1, l2, l3);
        }
        // ---- load B tile (16x64): 256 float4, 1 per thread ----
        {
            int row = tid >> 4, c4 = tid & 15;
            float4 f = *(const float4*)&B[(size_t)(k0 + row) * N + n0 + c4 * 4];
            uint32_t h0 = f2tf32(f.x), h1 = f2tf32(f.y), h2 = f2tf32(f.z), h3 = f2tf32(f.w);
            uint32_t l0 = f2tf32(f.x - __uint_as_float(h0));
            uint32_t l1 = f2tf32(f.y - __uint_as_float(h1));
            uint32_t l2 = f2tf32(f.z - __uint_as_float(h2));
            uint32_t l3 = f2tf32(f.w - __uint_as_float(h3));
            *(uint4*)&Bh[row][c4 * 4] = make_uint4(h0, h1, h2, h3);
            *(uint4*)&Bl[row][c4 * 4] = make_uint4(l0, l1, l2, l3);
        }
        __syncthreads();

#pragma unroll
        for (int kk = 0; kk < 2; kk++) {
            uint32_t ah[2][4], al[2][4], bh[4][2], bl[4][2];
#pragma unroll
            for (int fm = 0; fm < 2; fm++) {
                int r = wm * 32 + fm * 16;
                int cA = kk * 8 + tig;
                ah[fm][0] = Ah[r + gid][cA];         al[fm][0] = Al[r + gid][cA];
                ah[fm][1] = Ah[r + gid + 8][cA];     al[fm][1] = Al[r + gid + 8][cA];
                ah[fm][2] = Ah[r + gid][cA + 4];     al[fm][2] = Al[r + gid][cA + 4];
                ah[fm][3] = Ah[r + gid + 8][cA + 4]; al[fm][3] = Al[r + gid + 8][cA + 4];
            }
#pragma unroll
            for (int fn = 0; fn < 4; fn++) {
                int cc = wn * 32 + fn * 8 + gid;
                bh[fn][0] = Bh[kk * 8 + tig][cc];     bl[fn][0] = Bl[kk * 8 + tig][cc];
                bh[fn][1] = Bh[kk * 8 + tig + 4][cc]; bl[fn][1] = Bl[kk * 8 + tig + 4][cc];
            }
#pragma unroll
            for (int fm = 0; fm < 2; fm++)
#pragma unroll
                for (int fn = 0; fn < 4; fn++) {
                    mma_tf32(c_[fm][fn], ah[fm], bh[fn]);   // hi*hi
                    mma_tf32(c_[fm][fn], ah[fm], bl[fn]);   // hi*lo
                    mma_tf32(c_[fm][fn], al[fm], bh[fn]);   // lo*hi
                }
        }
        __syncthreads();
    }

    // ---- epilogue ----
#pragma unroll
    for (int fm = 0; fm < 2; fm++)
#pragma unroll
        for (int fn = 0; fn < 4; fn++) {
            int gm = m0 + wm * 32 + fm * 16 + gid;
            int gn = n0 + wn * 32 + fn * 8 + 2 * tig;
            if (gm < M)
                *(float2*)&C[(size_t)gm * N + gn] = make_float2(c_[fm][fn][0], c_[fm][fn][1]);
            if (gm + 8 < M)
                *(float2*)&C[(size_t)(gm + 8) * N + gn] = make_float2(c_[fm][fn][2], c_[fm][fn][3]);
        }
}

// ================= attention logits =================
__global__ void alpha_kernel(const float* __restrict__ h,
                             const float* __restrict__ a_src,
                             const float* __restrict__ a_dst,
                             float* __restrict__ as_out, float* __restrict__ ad_out,
                             int N)
{
    int gw = (blockIdx.x * blockDim.x + threadIdx.x) >> 5;
    int lane = threadIdx.x & 31;
    if (gw >= N * 2) return;
    int n = gw >> 1, hh = gw & 1;
    const float* hp = h + (size_t)n * DFEAT + hh * DHID;
    float4 v = *(const float4*)&hp[lane * 4];
    float4 s = *(const float4*)&a_src[hh * DHID + lane * 4];
    float4 d = *(const float4*)&a_dst[hh * DHID + lane * 4];
    float accs = v.x * s.x + v.y * s.y + v.z * s.z + v.w * s.w;
    float accd = v.x * d.x + v.y * d.y + v.z * d.z + v.w * d.w;
#pragma unroll
    for (int o = 16; o; o >>= 1) {
        accs += __shfl_xor_sync(0xffffffffu, accs, o);
        accd += __shfl_xor_sync(0xffffffffu, accd, o);
    }
    if (lane == 0) { as_out[gw] = accs; ad_out[gw] = accd; }
}

// ================= fused CSR softmax-aggregation =================
// One warp per (dst node, head); atomic-free single pass; deg from cursor-rowptr.
__global__ void agg_csr_kernel(const int* __restrict__ rowptr, const int* __restrict__ rowend,
                               const int* __restrict__ colidx,
                               const float* __restrict__ h,
                               const float* __restrict__ as_in, const float* __restrict__ ad_in,
                               float* __restrict__ out, int N)
{
    int gw = (blockIdx.x * blockDim.x + threadIdx.x) >> 5;
    int lane = threadIdx.x & 31;
    if (gw >= N * 2) return;
    int node = gw >> 1, head = gw & 1;
    int start = rowptr[node];
    int deg   = rowend[node] - start;
    float adv = ad_in[node * 2 + head];
    const float4* h4 = (const float4*)h + head * 32 + lane;

    float4 acc = make_float4(0.f, 0.f, 0.f, 0.f);
    float den = 0.f;

    int s = __ldg(&colidx[start]);   // deg >= 1 always (self loop)
    for (int i = 0; i < deg; i++) {
        int scur = s;
        if (i + 1 < deg) s = __ldg(&colidx[start + i + 1]);
        float e = __ldg(&as_in[scur * 2 + head]) + adv;
        e = e > 0.f ? e : NEG_SLOPE * e;
        float w = __expf(e);
        float4 v = h4[(size_t)scur * 64];
        den += w;
        acc.x = fmaf(w, v.x, acc.x);
        acc.y = fmaf(w, v.y, acc.y);
        acc.z = fmaf(w, v.z, acc.z);
        acc.w = fmaf(w, v.w, acc.w);
    }
    float r = 1.f / (den + EPSV);
    ((float4*)out)[(size_t)node * 64 + head * 32 + lane] =
        make_float4(acc.x * r, acc.y * r, acc.z * r, acc.w * r);
}

// ================= collapsed post-MLP =================
__global__ void wc_kernel(const float* __restrict__ Wp1, const float* __restrict__ bp1,
                          const float* __restrict__ Wp2, const float* __restrict__ bp2,
                          float* __restrict__ wc)
{
    int i = threadIdx.x;  // 256 threads
    float acc = 0.f;
    for (int j = 0; j < DHID; j++) acc += Wp1[i * DHID + j] * Wp2[j];
    wc[i] = acc;
    if (i == 0) {
        float b = 0.f;
        for (int j = 0; j < DHID; j++) b += bp1[j] * Wp2[j];
        wc[DFEAT] = b + bp2[0];
    }
}

__global__ void final_kernel(const float* __restrict__ agg2,
                             const float* __restrict__ b2,
                             const float* __restrict__ wc,
                             float* __restrict__ out, int N)
{
    int gw = (blockIdx.x * blockDim.x + threadIdx.x) >> 5;
    int lane = threadIdx.x & 31;
    if (gw >= N) return;
    const float* hp = agg2 + (size_t)gw * DFEAT;
    float acc = 0.f;
#pragma unroll
    for (int r = 0; r < 2; r++) {
        int cidx = r * 128 + lane * 4;
        float4 v  = *(const float4*)&hp[cidx];
        float4 bb = *(const float4*)&b2[cidx];
        float4 ww = *(const float4*)&wc[cidx];
        acc += fmaxf(v.x + bb.x, 0.f) * ww.x;
        acc += fmaxf(v.y + bb.y, 0.f) * ww.y;
        acc += fmaxf(v.z + bb.z, 0.f) * ww.z;
        acc += fmaxf(v.w + bb.w, 0.f) * ww.w;
    }
#pragma unroll
    for (int o = 16; o; o >>= 1) acc += __shfl_xor_sync(0xffffffffu, acc, o);
    if (lane == 0) {
        float z = acc + wc[DFEAT];
        out[gw] = 1.f / (1.f + expf(-z));
    }
}

// ================= launch =================
extern "C" void kernel_launch(void* const* d_in, const int* in_sizes, int n_in,
                              void* d_out, int out_size)
{
    const float* x      = (const float*)d_in[0];
    const int*   ei     = (const int*)  d_in[1];
    const float* W1     = (const float*)d_in[2];
    const float* a_src1 = (const float*)d_in[3];
    const float* a_dst1 = (const float*)d_in[4];
    const float* b1     = (const float*)d_in[5];
    const float* W2     = (const float*)d_in[6];
    const float* a_src2 = (const float*)d_in[7];
    const float* a_dst2 = (const float*)d_in[8];
    const float* b2     = (const float*)d_in[9];
    const float* Wp1    = (const float*)d_in[10];
    const float* bp1    = (const float*)d_in[11];
    const float* Wp2    = (const float*)d_in[12];
    const float* bp2    = (const float*)d_in[13];

    const int N = in_sizes[0] / 128;
    const int E = in_sizes[1] / 2;
    const int Etot = E + N;

    float *h1, *agg1, *h2, *agg2, *as, *ad, *wc;
    int *cnt, *rowptr, *cursor, *colidx, *bsum;
    cudaGetSymbolAddress((void**)&h1,   g_h1);
    cudaGetSymbolAddress((void**)&agg1, g_agg1);
    cudaGetSymbolAddress((void**)&h2,   g_h2);
    cudaGetSymbolAddress((void**)&agg2, g_agg2);
    cudaGetSymbolAddress((void**)&as,   g_as);
    cudaGetSymbolAddress((void**)&ad,   g_ad);
    cudaGetSymbolAddress((void**)&wc,   g_wc);
    cudaGetSymbolAddress((void**)&cnt,    g_cnt);
    cudaGetSymbolAddress((void**)&rowptr, g_rowptr);
    cudaGetSymbolAddress((void**)&cursor, g_cursor);
    cudaGetSymbolAddress((void**)&colidx, g_colidx);
    cudaGetSymbolAddress((void**)&bsum,   g_bsum);

    const int nb = (N + 255) / 256;
    dim3 gemm_grid((N + 127) / 128, DFEAT / 64);
    const int agg_blocks   = (N * 2 * 32 + 255) / 256;
    const int final_blocks = (N * 32 + 255) / 256;
    const int edge_blocks  = (Etot + 255) / 256;

    // 1-3: CSR front half (cnt is zero from init / previous replay's scan_final)
    count_kernel<<<edge_blocks, 256>>>(ei, cnt, E, Etot);
    scan_block_sums<<<nb, 256>>>(cnt, bsum, N);
    scan_bsums<<<1, 256>>>(bsum, nb);
    // 4: gemm1 (profile slot — unfused flavor, want regs/occ)
    gemm_tf32_kernel<0><<<gemm_grid, 256>>>(x, W1, nullptr, h1, N, DFEAT, 128);
    // 5-6: finish CSR (scan_final re-zeroes cnt for next replay)
    scan_final<<<nb, 256>>>(cnt, bsum, rowptr, cursor, N);
    scatter_kernel<<<edge_blocks, 256>>>(ei, cursor, colidx, E, Etot);
    // 7-8: layer-1 logits + aggregation (cursor = row end)
    alpha_kernel<<<agg_blocks, 256>>>(h1, a_src1, a_dst1, as, ad, N);
    agg_csr_kernel<<<agg_blocks, 256>>>(rowptr, cursor, colidx, h1, as, ad, agg1, N);
    // 9-11: layer 2 (input = relu(agg1 + b1), fused into GEMM A-load)
    gemm_tf32_kernel<1><<<gemm_grid, 256>>>(agg1, W2, b1, h2, N, DFEAT, DFEAT);
    alpha_kernel<<<agg_blocks, 256>>>(h2, a_src2, a_dst2, as, ad, N);
    agg_csr_kernel<<<agg_blocks, 256>>>(rowptr, cursor, colidx, h2, as, ad, agg2, N);
    // 12-13: collapsed post-MLP + sigmoid
    wc_kernel<<<1, 256>>>(Wp1, bp1, Wp2, bp2, wc);
    final_kernel<<<final_blocks, 256>>>(agg2, b2, wc, (float*)d_out, N);
}

// round 8
// speedup vs baseline: 1.2076x; 1.2076x over previous
#include <cuda_runtime.h>
#include <cuda_fp16.h>
#include <math.h>
#include <stdint.h>

#define NNODES 50000
#define EEDGES 800000
#define ETOT   (EEDGES + NNODES)
#define DHID   128
#define DFEAT  256          // HEADS * HID
#define NEG_SLOPE 0.2f
#define EPSV 1e-16f

// ---------------- scratch (no allocation allowed; zero-initialized at load) ----------------
__device__ __half g_h1[NNODES * DFEAT];
__device__ float  g_agg1[NNODES * DFEAT];
__device__ __half g_h2[NNODES * DFEAT];
__device__ float  g_agg2[NNODES * DFEAT];
__device__ float  g_as[NNODES * 2];
__device__ float  g_ad[NNODES * 2];
__device__ float  g_wc[DFEAT + 1];
__device__ int    g_cnt[NNODES];      // self-cleaning (scan_final re-zeroes)
__device__ int    g_rowptr[NNODES];
__device__ int    g_cursor[NNODES];   // after scatter: row end
__device__ int    g_colidx[ETOT];
__device__ int    g_bsum[256];

// ================= CSR construction =================
__global__ void count_kernel(const int* __restrict__ ei, int* __restrict__ cnt,
                             int E, int Etot) {
    int t = blockIdx.x * blockDim.x + threadIdx.x;
    if (t >= Etot) return;
    int d = (t < E) ? ei[E + t] : (t - E);
    atomicAdd(&cnt[d], 1);
}

__global__ void scan_block_sums(const int* __restrict__ cnt, int* __restrict__ bsum, int N) {
    __shared__ int sh[256];
    int tid = threadIdx.x;
    int i = blockIdx.x * 256 + tid;
    sh[tid] = (i < N) ? cnt[i] : 0;
    __syncthreads();
    for (int s = 128; s > 0; s >>= 1) {
        if (tid < s) sh[tid] += sh[tid + s];
        __syncthreads();
    }
    if (tid == 0) bsum[blockIdx.x] = sh[0];
}

__global__ void scan_bsums(int* bsum, int nb) {
    __shared__ int sh[256];
    int tid = threadIdx.x;
    int v0 = (tid < nb) ? bsum[tid] : 0;
    sh[tid] = v0;
    __syncthreads();
    for (int off = 1; off < 256; off <<= 1) {
        int v = (tid >= off) ? sh[tid - off] : 0;
        __syncthreads();
        sh[tid] += v;
        __syncthreads();
    }
    if (tid < nb) bsum[tid] = sh[tid] - v0;   // exclusive
}

__global__ void scan_final(int* __restrict__ cnt, const int* __restrict__ bsum,
                           int* __restrict__ rowptr, int* __restrict__ cursor, int N) {
    __shared__ int sh[256];
    int tid = threadIdx.x;
    int i = blockIdx.x * 256 + tid;
    int v0 = (i < N) ? cnt[i] : 0;
    sh[tid] = v0;
    __syncthreads();
    for (int off = 1; off < 256; off <<= 1) {
        int v = (tid >= off) ? sh[tid - off] : 0;
        __syncthreads();
        sh[tid] += v;
        __syncthreads();
    }
    if (i < N) {
        int excl = sh[tid] - v0 + bsum[blockIdx.x];
        rowptr[i] = excl;
        cursor[i] = excl;
        cnt[i] = 0;   // self-clean for next graph replay
    }
}

__global__ void scatter_kernel(const int* __restrict__ ei, int* __restrict__ cursor,
                               int* __restrict__ colidx, int E, int Etot) {
    int t = blockIdx.x * blockDim.x + threadIdx.x;
    if (t >= Etot) return;
    int s, d;
    if (t < E) { s = ei[t]; d = ei[E + t]; } else { s = d = t - E; }
    int pos = atomicAdd(&cursor[d], 1);
    colidx[pos] = s;
}

// ================= 3xTF32 tensor-core GEMM (R2 mainloop — register budget sacred) =================
// C output is fp16 (consumed only by alpha dots + edge gather).
__device__ __forceinline__ uint32_t f2tf32(float f) {
    uint32_t u;
    asm("cvt.rna.tf32.f32 %0, %1;" : "=r"(u) : "f"(f));
    return u;
}

__device__ __forceinline__ void mma_tf32(float* c, const uint32_t* a, const uint32_t* b) {
    asm volatile(
        "mma.sync.aligned.m16n8k8.row.col.f32.tf32.tf32.f32 "
        "{%0,%1,%2,%3}, {%4,%5,%6,%7}, {%8,%9}, {%0,%1,%2,%3};"
        : "+f"(c[0]), "+f"(c[1]), "+f"(c[2]), "+f"(c[3])
        : "r"(a[0]), "r"(a[1]), "r"(a[2]), "r"(a[3]), "r"(b[0]), "r"(b[1]));
}

template <int FUSE_RELU>
__global__ void __launch_bounds__(256) gemm_tf32_kernel(
    const float* __restrict__ A, const float* __restrict__ B,
    const float* __restrict__ bias, __half* __restrict__ C,
    int M, int N, int K)
{
    __shared__ uint32_t Ah[128][20];   // pad 4: frag bank = 4*gid+tig (bijective)
    __shared__ uint32_t Al[128][20];
    __shared__ uint32_t Bh[16][72];    // pad 8: frag bank = 8*tig+gid (bijective)
    __shared__ uint32_t Bl[16][72];

    const int tid  = threadIdx.x;
    const int lane = tid & 31;
    const int warp = tid >> 5;
    const int wm   = warp & 3;     // m warp: wm*32
    const int wn   = warp >> 2;    // n warp: wn*32
    const int gid  = lane >> 2;
    const int tig  = lane & 3;
    const int m0 = blockIdx.x * 128;
    const int n0 = blockIdx.y * 64;

    float c_[2][4][4];
#pragma unroll
    for (int fm = 0; fm < 2; fm++)
#pragma unroll
        for (int fn = 0; fn < 4; fn++)
#pragma unroll
            for (int j = 0; j < 4; j++) c_[fm][fn][j] = 0.f;

    for (int k0 = 0; k0 < K; k0 += 16) {
        // ---- load A tile (128x16): 512 float4, 2 per thread ----
#pragma unroll
        for (int it = 0; it < 2; it++) {
            int idx = tid + it * 256;
            int row = idx >> 2, c4 = idx & 3;
            int gm = m0 + row;
            float4 f = make_float4(0.f, 0.f, 0.f, 0.f);
            if (gm < M) f = *(const float4*)&A[(size_t)gm * K + k0 + c4 * 4];
            if (FUSE_RELU) {
                float4 bb = *(const float4*)&bias[k0 + c4 * 4];
                f.x = fmaxf(f.x + bb.x, 0.f);
                f.y = fmaxf(f.y + bb.y, 0.f);
                f.z = fmaxf(f.z + bb.z, 0.f);
                f.w = fmaxf(f.w + bb.w, 0.f);
            }
            uint32_t h0 = f2tf32(f.x), h1 = f2tf32(f.y), h2 = f2tf32(f.z), h3 = f2tf32(f.w);
            uint32_t l0 = f2tf32(f.x - __uint_as_float(h0));
            uint32_t l1 = f2tf32(f.y - __uint_as_float(h1));
            uint32_t l2 = f2tf32(f.z - __uint_as_float(h2));
            uint32_t l3 = f2tf32(f.w - __uint_as_float(h3));
            *(uint4*)&Ah[row][c4 * 4] = make_uint4(h0, h1, h2, h3);
            *(uint4*)&Al[row][c4 * 4] = make_uint4(l0, l1, l2, l3);
        }
        // ---- load B tile (16x64): 256 float4, 1 per thread ----
        {
            int row = tid >> 4, c4 = tid & 15;
            float4 f = *(const float4*)&B[(size_t)(k0 + row) * N + n0 + c4 * 4];
            uint32_t h0 = f2tf32(f.x), h1 = f2tf32(f.y), h2 = f2tf32(f.z), h3 = f2tf32(f.w);
            uint32_t l0 = f2tf32(f.x - __uint_as_float(h0));
            uint32_t l1 = f2tf32(f.y - __uint_as_float(h1));
            uint32_t l2 = f2tf32(f.z - __uint_as_float(h2));
            uint32_t l3 = f2tf32(f.w - __uint_as_float(h3));
            *(uint4*)&Bh[row][c4 * 4] = make_uint4(h0, h1, h2, h3);
            *(uint4*)&Bl[row][c4 * 4] = make_uint4(l0, l1, l2, l3);
        }
        __syncthreads();

#pragma unroll
        for (int kk = 0; kk < 2; kk++) {
            uint32_t ah[2][4], al[2][4], bh[4][2], bl[4][2];
#pragma unroll
            for (int fm = 0; fm < 2; fm++) {
                int r = wm * 32 + fm * 16;
                int cA = kk * 8 + tig;
                ah[fm][0] = Ah[r + gid][cA];         al[fm][0] = Al[r + gid][cA];
                ah[fm][1] = Ah[r + gid + 8][cA];     al[fm][1] = Al[r + gid + 8][cA];
                ah[fm][2] = Ah[r + gid][cA + 4];     al[fm][2] = Al[r + gid][cA + 4];
                ah[fm][3] = Ah[r + gid + 8][cA + 4]; al[fm][3] = Al[r + gid + 8][cA + 4];
            }
#pragma unroll
            for (int fn = 0; fn < 4; fn++) {
                int cc = wn * 32 + fn * 8 + gid;
                bh[fn][0] = Bh[kk * 8 + tig][cc];     bl[fn][0] = Bl[kk * 8 + tig][cc];
                bh[fn][1] = Bh[kk * 8 + tig + 4][cc]; bl[fn][1] = Bl[kk * 8 + tig + 4][cc];
            }
#pragma unroll
            for (int fm = 0; fm < 2; fm++)
#pragma unroll
                for (int fn = 0; fn < 4; fn++) {
                    mma_tf32(c_[fm][fn], ah[fm], bh[fn]);   // hi*hi
                    mma_tf32(c_[fm][fn], ah[fm], bl[fn]);   // hi*lo
                    mma_tf32(c_[fm][fn], al[fm], bh[fn]);   // lo*hi
                }
        }
        __syncthreads();
    }

    // ---- epilogue: fp16 stores ----
#pragma unroll
    for (int fm = 0; fm < 2; fm++)
#pragma unroll
        for (int fn = 0; fn < 4; fn++) {
            int gm = m0 + wm * 32 + fm * 16 + gid;
            int gn = n0 + wn * 32 + fn * 8 + 2 * tig;
            if (gm < M)
                *(__half2*)&C[(size_t)gm * N + gn] =
                    __floats2half2_rn(c_[fm][fn][0], c_[fm][fn][1]);
            if (gm + 8 < M)
                *(__half2*)&C[(size_t)(gm + 8) * N + gn] =
                    __floats2half2_rn(c_[fm][fn][2], c_[fm][fn][3]);
        }
}

// ================= attention logits (fp16 h) =================
__global__ void alpha_kernel(const __half* __restrict__ h,
                             const float* __restrict__ a_src,
                             const float* __restrict__ a_dst,
                             float* __restrict__ as_out, float* __restrict__ ad_out,
                             int N)
{
    int gw = (blockIdx.x * blockDim.x + threadIdx.x) >> 5;
    int lane = threadIdx.x & 31;
    if (gw >= N * 2) return;
    int n = gw >> 1, hh = gw & 1;
    const __half2* hp = (const __half2*)(h + (size_t)n * DFEAT + hh * DHID);
    __half2 p0 = hp[lane * 2], p1 = hp[lane * 2 + 1];
    float2 f0 = __half22float2(p0), f1 = __half22float2(p1);
    float4 s = *(const float4*)&a_src[hh * DHID + lane * 4];
    float4 d = *(const float4*)&a_dst[hh * DHID + lane * 4];
    float accs = f0.x * s.x + f0.y * s.y + f1.x * s.z + f1.y * s.w;
    float accd = f0.x * d.x + f0.y * d.y + f1.x * d.z + f1.y * d.w;
#pragma unroll
    for (int o = 16; o; o >>= 1) {
        accs += __shfl_xor_sync(0xffffffffu, accs, o);
        accd += __shfl_xor_sync(0xffffffffu, accd, o);
    }
    if (lane == 0) { as_out[gw] = accs; ad_out[gw] = accd; }
}

// ================= fused CSR softmax-aggregation (fp16 gather, warp-per-node) =================
// Lane l owns fp16 elements [8l, 8l+8) of the 256-wide feature row:
// lanes 0-15 -> head 0, lanes 16-31 -> head 1. One uint4 gather per lane per edge.
__global__ void agg_csr_kernel(const int* __restrict__ rowptr, const int* __restrict__ rowend,
                               const int* __restrict__ colidx,
                               const __half* __restrict__ h,
                               const float* __restrict__ as_in, const float* __restrict__ ad_in,
                               float* __restrict__ out, int N)
{
    int gw = (blockIdx.x * blockDim.x + threadIdx.x) >> 5;
    int lane = threadIdx.x & 31;
    if (gw >= N) return;
    int start = rowptr[gw];
    int end   = rowend[gw];
    float2 adv = ((const float2*)ad_in)[gw];
    const uint4* h4 = (const uint4*)h;   // 8 fp16 per uint4; node stride = 32

    float acc[8];
#pragma unroll
    for (int j = 0; j < 8; j++) acc[j] = 0.f;
    float den0 = 0.f, den1 = 0.f;
    const bool head0 = lane < 16;

    for (int i = start; i < end; i++) {
        int s = __ldg(&colidx[i]);
        float2 av = ((const float2*)as_in)[s];
        float e0 = av.x + adv.x;  e0 = e0 > 0.f ? e0 : NEG_SLOPE * e0;
        float e1 = av.y + adv.y;  e1 = e1 > 0.f ? e1 : NEG_SLOPE * e1;
        float w0 = __expf(e0);
        float w1 = __expf(e1);
        den0 += w0;  den1 += w1;
        float w = head0 ? w0 : w1;
        uint4 v = h4[(size_t)s * 32 + lane];
        float2 a = __half22float2(*(const __half2*)&v.x);
        float2 b = __half22float2(*(const __half2*)&v.y);
        float2 c = __half22float2(*(const __half2*)&v.z);
        float2 d = __half22float2(*(const __half2*)&v.w);
        acc[0] = fmaf(w, a.x, acc[0]); acc[1] = fmaf(w, a.y, acc[1]);
        acc[2] = fmaf(w, b.x, acc[2]); acc[3] = fmaf(w, b.y, acc[3]);
        acc[4] = fmaf(w, c.x, acc[4]); acc[5] = fmaf(w, c.y, acc[5]);
        acc[6] = fmaf(w, d.x, acc[6]); acc[7] = fmaf(w, d.y, acc[7]);
    }
    float r = 1.f / ((head0 ? den0 : den1) + EPSV);
    float* op = out + (size_t)gw * DFEAT + lane * 8;
    *(float4*)op       = make_float4(acc[0] * r, acc[1] * r, acc[2] * r, acc[3] * r);
    *(float4*)(op + 4) = make_float4(acc[4] * r, acc[5] * r, acc[6] * r, acc[7] * r);
}

// ================= collapsed post-MLP =================
__global__ void wc_kernel(const float* __restrict__ Wp1, const float* __restrict__ bp1,
                          const float* __restrict__ Wp2, const float* __restrict__ bp2,
                          float* __restrict__ wc)
{
    int i = threadIdx.x;  // 256 threads
    float acc = 0.f;
    for (int j = 0; j < DHID; j++) acc += Wp1[i * DHID + j] * Wp2[j];
    wc[i] = acc;
    if (i == 0) {
        float b = 0.f;
        for (int j = 0; j < DHID; j++) b += bp1[j] * Wp2[j];
        wc[DFEAT] = b + bp2[0];
    }
}

__global__ void final_kernel(const float* __restrict__ agg2,
                             const float* __restrict__ b2,
                             const float* __restrict__ wc,
                             float* __restrict__ out, int N)
{
    int gw = (blockIdx.x * blockDim.x + threadIdx.x) >> 5;
    int lane = threadIdx.x & 31;
    if (gw >= N) return;
    const float* hp = agg2 + (size_t)gw * DFEAT;
    float acc = 0.f;
#pragma unroll
    for (int r = 0; r < 2; r++) {
        int cidx = r * 128 + lane * 4;
        float4 v  = *(const float4*)&hp[cidx];
        float4 bb = *(const float4*)&b2[cidx];
        float4 ww = *(const float4*)&wc[cidx];
        acc += fmaxf(v.x + bb.x, 0.f) * ww.x;
        acc += fmaxf(v.y + bb.y, 0.f) * ww.y;
        acc += fmaxf(v.z + bb.z, 0.f) * ww.z;
        acc += fmaxf(v.w + bb.w, 0.f) * ww.w;
    }
#pragma unroll
    for (int o = 16; o; o >>= 1) acc += __shfl_xor_sync(0xffffffffu, acc, o);
    if (lane == 0) {
        float z = acc + wc[DFEAT];
        out[gw] = 1.f / (1.f + expf(-z));
    }
}

// ================= launch =================
extern "C" void kernel_launch(void* const* d_in, const int* in_sizes, int n_in,
                              void* d_out, int out_size)
{
    const float* x      = (const float*)d_in[0];
    const int*   ei     = (const int*)  d_in[1];
    const float* W1     = (const float*)d_in[2];
    const float* a_src1 = (const float*)d_in[3];
    const float* a_dst1 = (const float*)d_in[4];
    const float* b1     = (const float*)d_in[5];
    const float* W2     = (const float*)d_in[6];
    const float* a_src2 = (const float*)d_in[7];
    const float* a_dst2 = (const float*)d_in[8];
    const float* b2     = (const float*)d_in[9];
    const float* Wp1    = (const float*)d_in[10];
    const float* bp1    = (const float*)d_in[11];
    const float* Wp2    = (const float*)d_in[12];
    const float* bp2    = (const float*)d_in[13];

    const int N = in_sizes[0] / 128;
    const int E = in_sizes[1] / 2;
    const int Etot = E + N;

    __half *h1, *h2;
    float *agg1, *agg2, *as, *ad, *wc;
    int *cnt, *rowptr, *cursor, *colidx, *bsum;
    cudaGetSymbolAddress((void**)&h1,   g_h1);
    cudaGetSymbolAddress((void**)&agg1, g_agg1);
    cudaGetSymbolAddress((void**)&h2,   g_h2);
    cudaGetSymbolAddress((void**)&agg2, g_agg2);
    cudaGetSymbolAddress((void**)&as,   g_as);
    cudaGetSymbolAddress((void**)&ad,   g_ad);
    cudaGetSymbolAddress((void**)&wc,   g_wc);
    cudaGetSymbolAddress((void**)&cnt,    g_cnt);
    cudaGetSymbolAddress((void**)&rowptr, g_rowptr);
    cudaGetSymbolAddress((void**)&cursor, g_cursor);
    cudaGetSymbolAddress((void**)&colidx, g_colidx);
    cudaGetSymbolAddress((void**)&bsum,   g_bsum);

    const int nb = (N + 255) / 256;
    dim3 gemm_grid((N + 127) / 128, DFEAT / 64);
    const int aa_blocks    = (N * 2 * 32 + 255) / 256;
    const int agg_blocks   = (N * 32 + 255) / 256;
    const int final_blocks = (N * 32 + 255) / 256;
    const int edge_blocks  = (Etot + 255) / 256;

    // 1-3: CSR front half (cnt zero from init / previous replay's scan_final)
    count_kernel<<<edge_blocks, 256>>>(ei, cnt, E, Etot);
    scan_block_sums<<<nb, 256>>>(cnt, bsum, N);
    scan_bsums<<<1, 256>>>(bsum, nb);
    // 4: gemm1 (profile slot)
    gemm_tf32_kernel<0><<<gemm_grid, 256>>>(x, W1, nullptr, h1, N, DFEAT, 128);
    // 5-6: finish CSR
    scan_final<<<nb, 256>>>(cnt, bsum, rowptr, cursor, N);
    scatter_kernel<<<edge_blocks, 256>>>(ei, cursor, colidx, E, Etot);
    // 7-8: layer-1 logits + aggregation
    alpha_kernel<<<aa_blocks, 256>>>(h1, a_src1, a_dst1, as, ad, N);
    agg_csr_kernel<<<agg_blocks, 256>>>(rowptr, cursor, colidx, h1, as, ad, agg1, N);
    // 9-11: layer 2 (input = relu(agg1 + b1), fused into GEMM A-load)
    gemm_tf32_kernel<1><<<gemm_grid, 256>>>(agg1, W2, b1, h2, N, DFEAT, DFEAT);
    alpha_kernel<<<aa_blocks, 256>>>(h2, a_src2, a_dst2, as, ad, N);
    agg_csr_kernel<<<agg_blocks, 256>>>(rowptr, cursor, colidx, h2, as, ad, agg2, N);
    // 12-13: collapsed post-MLP + sigmoid
    wc_kernel<<<1, 256>>>(Wp1, bp1, Wp2, bp2, wc);
    final_kernel<<<final_blocks, 256>>>(agg2, b2, wc, (float*)d_out, N);
}

// round 9
// speedup vs baseline: 1.4189x; 1.1749x over previous
#include <cuda_runtime.h>
#include <cuda_fp16.h>
#include <math.h>
#include <stdint.h>

#define NNODES 50000
#define EEDGES 800000
#define ETOT   (EEDGES + NNODES)
#define DHID   128
#define DFEAT  256          // HEADS * HID
#define NEG_SLOPE 0.2f
#define EPSV 1e-16f

// ---------------- scratch (no allocation allowed; zero-initialized at load) ----------------
__device__ __half g_h1[NNODES * DFEAT];
__device__ float  g_agg1[NNODES * DFEAT];
__device__ __half g_h2[NNODES * DFEAT];
__device__ float  g_agg2[NNODES * DFEAT];
__device__ float  g_as[NNODES * 2];
__device__ float  g_ad[NNODES * 2];
__device__ float  g_wc[DFEAT + 1];
__device__ uint32_t g_w1hi[DFEAT * DHID / 2];   // W1 split, packed k-pairs [N][K/2]
__device__ uint32_t g_w1lo[DFEAT * DHID / 2];
__device__ uint32_t g_w2hi[DFEAT * DFEAT / 2];  // W2 split
__device__ uint32_t g_w2lo[DFEAT * DFEAT / 2];
__device__ int    g_cnt[NNODES];      // self-cleaning (scan_final re-zeroes)
__device__ int    g_rowptr[NNODES];
__device__ int    g_cursor[NNODES];   // after scatter: row end
__device__ int    g_colidx[ETOT];
__device__ int    g_bsum[256];

// ================= weight pre-split: W[k][n] fp32 -> hi/lo fp16 k-pairs [n][k/2] =================
__global__ void wsplit_kernel(const float* __restrict__ W,
                              uint32_t* __restrict__ hi, uint32_t* __restrict__ lo,
                              int K, int N) {
    int t = blockIdx.x * 256 + threadIdx.x;
    int total = N * (K >> 1);
    if (t >= total) return;
    int n = t / (K >> 1), k2 = t % (K >> 1);
    float x = W[(size_t)(2 * k2) * N + n];
    float y = W[(size_t)(2 * k2 + 1) * N + n];
    __half2 h = __floats2half2_rn(x, y);
    float2 hf = __half22float2(h);
    __half2 l = __floats2half2_rn(x - hf.x, y - hf.y);
    hi[t] = *(uint32_t*)&h;
    lo[t] = *(uint32_t*)&l;
}

// ================= CSR construction =================
__global__ void count_kernel(const int* __restrict__ ei, int* __restrict__ cnt,
                             int E, int Etot) {
    int t = blockIdx.x * blockDim.x + threadIdx.x;
    if (t >= Etot) return;
    int d = (t < E) ? ei[E + t] : (t - E);
    atomicAdd(&cnt[d], 1);
}

__global__ void scan_block_sums(const int* __restrict__ cnt, int* __restrict__ bsum, int N) {
    __shared__ int sh[256];
    int tid = threadIdx.x;
    int i = blockIdx.x * 256 + tid;
    sh[tid] = (i < N) ? cnt[i] : 0;
    __syncthreads();
    for (int s = 128; s > 0; s >>= 1) {
        if (tid < s) sh[tid] += sh[tid + s];
        __syncthreads();
    }
    if (tid == 0) bsum[blockIdx.x] = sh[0];
}

__global__ void scan_bsums(int* bsum, int nb) {
    __shared__ int sh[256];
    int tid = threadIdx.x;
    int v0 = (tid < nb) ? bsum[tid] : 0;
    sh[tid] = v0;
    __syncthreads();
    for (int off = 1; off < 256; off <<= 1) {
        int v = (tid >= off) ? sh[tid - off] : 0;
        __syncthreads();
        sh[tid] += v;
        __syncthreads();
    }
    if (tid < nb) bsum[tid] = sh[tid] - v0;   // exclusive
}

__global__ void scan_final(int* __restrict__ cnt, const int* __restrict__ bsum,
                           int* __restrict__ rowptr, int* __restrict__ cursor, int N) {
    __shared__ int sh[256];
    int tid = threadIdx.x;
    int i = blockIdx.x * 256 + tid;
    int v0 = (i < N) ? cnt[i] : 0;
    sh[tid] = v0;
    __syncthreads();
    for (int off = 1; off < 256; off <<= 1) {
        int v = (tid >= off) ? sh[tid - off] : 0;
        __syncthreads();
        sh[tid] += v;
        __syncthreads();
    }
    if (i < N) {
        int excl = sh[tid] - v0 + bsum[blockIdx.x];
        rowptr[i] = excl;
        cursor[i] = excl;
        cnt[i] = 0;   // self-clean for next graph replay
    }
}

__global__ void scatter_kernel(const int* __restrict__ ei, int* __restrict__ cursor,
                               int* __restrict__ colidx, int E, int Etot) {
    int t = blockIdx.x * blockDim.x + threadIdx.x;
    if (t >= Etot) return;
    int s, d;
    if (t < E) { s = ei[t]; d = ei[E + t]; } else { s = d = t - E; }
    int pos = atomicAdd(&cursor[d], 1);
    colidx[pos] = s;
}

// ================= double-fp16 tensor-core GEMM =================
// C[M][N] (fp16 out) = op(A)[M][K] @ W[K][N]; W pre-split into hi/lo k-pair arrays.
// 3-term compensated: hi*hi + hi*lo + lo*hi (lo*lo ~2^-22 dropped).
__device__ __forceinline__ void mma_f16(float* c, const uint32_t* a, const uint32_t* b) {
    asm volatile(
        "mma.sync.aligned.m16n8k16.row.col.f32.f16.f16.f32 "
        "{%0,%1,%2,%3}, {%4,%5,%6,%7}, {%8,%9}, {%0,%1,%2,%3};"
        : "+f"(c[0]), "+f"(c[1]), "+f"(c[2]), "+f"(c[3])
        : "r"(a[0]), "r"(a[1]), "r"(a[2]), "r"(a[3]), "r"(b[0]), "r"(b[1]));
}

template <int FUSE_RELU>
__global__ void __launch_bounds__(256) gemm_f16_kernel(
    const float* __restrict__ A,
    const uint32_t* __restrict__ Whi, const uint32_t* __restrict__ Wlo,
    const float* __restrict__ bias, __half* __restrict__ C,
    int M, int N, int K)
{
    __shared__ uint32_t Ah[128][12];   // [row][k2], pad 12: frag bank 12*gid+tig bijective
    __shared__ uint32_t Al[128][12];
    __shared__ uint32_t Bh[64][12];    // [n][k2]
    __shared__ uint32_t Bl[64][12];

    const int tid  = threadIdx.x;
    const int lane = tid & 31;
    const int warp = tid >> 5;
    const int wm   = warp & 3;     // m warp: wm*32
    const int wn   = warp >> 2;    // n warp: wn*32
    const int gid  = lane >> 2;
    const int tig  = lane & 3;
    const int m0 = blockIdx.x * 128;
    const int n0 = blockIdx.y * 64;
    const int K2 = K >> 1;

    float c_[2][4][4];
#pragma unroll
    for (int fm = 0; fm < 2; fm++)
#pragma unroll
        for (int fn = 0; fn < 4; fn++)
#pragma unroll
            for (int j = 0; j < 4; j++) c_[fm][fn][j] = 0.f;

    for (int k0 = 0; k0 < K; k0 += 16) {
        // ---- A tile (128 x 16): 512 float4, 2 per thread; split to hi/lo k-pairs ----
#pragma unroll
        for (int it = 0; it < 2; it++) {
            int idx = tid + it * 256;
            int row = idx >> 2, c4 = idx & 3;
            int gm = m0 + row;
            float4 f = make_float4(0.f, 0.f, 0.f, 0.f);
            if (gm < M) f = *(const float4*)&A[(size_t)gm * K + k0 + c4 * 4];
            if (FUSE_RELU) {
                float4 bb = *(const float4*)&bias[k0 + c4 * 4];
                f.x = fmaxf(f.x + bb.x, 0.f);
                f.y = fmaxf(f.y + bb.y, 0.f);
                f.z = fmaxf(f.z + bb.z, 0.f);
                f.w = fmaxf(f.w + bb.w, 0.f);
            }
            __half2 h01 = __floats2half2_rn(f.x, f.y);
            __half2 h23 = __floats2half2_rn(f.z, f.w);
            float2 hf01 = __half22float2(h01);
            float2 hf23 = __half22float2(h23);
            __half2 l01 = __floats2half2_rn(f.x - hf01.x, f.y - hf01.y);
            __half2 l23 = __floats2half2_rn(f.z - hf23.x, f.w - hf23.y);
            *(uint2*)&Ah[row][c4 * 2] = make_uint2(*(uint32_t*)&h01, *(uint32_t*)&h23);
            *(uint2*)&Al[row][c4 * 2] = make_uint2(*(uint32_t*)&l01, *(uint32_t*)&l23);
        }
        // ---- B tile (64 n x 8 k2): 256 uint2, 1 per thread (pre-split weights) ----
        {
            int n = tid >> 2;             // 0..63
            int kq = (tid & 3) * 2;       // 0,2,4,6
            size_t gidx = (size_t)(n0 + n) * K2 + (k0 >> 1) + kq;
            uint2 hv = *(const uint2*)&Whi[gidx];
            uint2 lv = *(const uint2*)&Wlo[gidx];
            *(uint2*)&Bh[n][kq] = hv;
            *(uint2*)&Bl[n][kq] = lv;
        }
        __syncthreads();

        uint32_t ah[2][4], al[2][4], bh[4][2], bl[4][2];
#pragma unroll
        for (int fm = 0; fm < 2; fm++) {
            int r = wm * 32 + fm * 16;
            ah[fm][0] = Ah[r + gid][tig];       al[fm][0] = Al[r + gid][tig];
            ah[fm][1] = Ah[r + gid + 8][tig];   al[fm][1] = Al[r + gid + 8][tig];
            ah[fm][2] = Ah[r + gid][tig + 4];   al[fm][2] = Al[r + gid][tig + 4];
            ah[fm][3] = Ah[r + gid + 8][tig + 4]; al[fm][3] = Al[r + gid + 8][tig + 4];
        }
#pragma unroll
        for (int fn = 0; fn < 4; fn++) {
            int cc = wn * 32 + fn * 8 + gid;
            bh[fn][0] = Bh[cc][tig];     bl[fn][0] = Bl[cc][tig];
            bh[fn][1] = Bh[cc][tig + 4]; bl[fn][1] = Bl[cc][tig + 4];
        }
#pragma unroll
        for (int fm = 0; fm < 2; fm++)
#pragma unroll
            for (int fn = 0; fn < 4; fn++) {
                mma_f16(c_[fm][fn], ah[fm], bh[fn]);   // hi*hi
                mma_f16(c_[fm][fn], ah[fm], bl[fn]);   // hi*lo
                mma_f16(c_[fm][fn], al[fm], bh[fn]);   // lo*hi
            }
        __syncthreads();
    }

    // ---- epilogue: fp16 stores ----
#pragma unroll
    for (int fm = 0; fm < 2; fm++)
#pragma unroll
        for (int fn = 0; fn < 4; fn++) {
            int gm = m0 + wm * 32 + fm * 16 + gid;
            int gn = n0 + wn * 32 + fn * 8 + 2 * tig;
            if (gm < M)
                *(__half2*)&C[(size_t)gm * N + gn] =
                    __floats2half2_rn(c_[fm][fn][0], c_[fm][fn][1]);
            if (gm + 8 < M)
                *(__half2*)&C[(size_t)(gm + 8) * N + gn] =
                    __floats2half2_rn(c_[fm][fn][2], c_[fm][fn][3]);
        }
}

// ================= attention logits (fp16 h) =================
__global__ void alpha_kernel(const __half* __restrict__ h,
                             const float* __restrict__ a_src,
                             const float* __restrict__ a_dst,
                             float* __restrict__ as_out, float* __restrict__ ad_out,
                             int N)
{
    int gw = (blockIdx.x * blockDim.x + threadIdx.x) >> 5;
    int lane = threadIdx.x & 31;
    if (gw >= N * 2) return;
    int n = gw >> 1, hh = gw & 1;
    const __half2* hp = (const __half2*)(h + (size_t)n * DFEAT + hh * DHID);
    __half2 p0 = hp[lane * 2], p1 = hp[lane * 2 + 1];
    float2 f0 = __half22float2(p0), f1 = __half22float2(p1);
    float4 s = *(const float4*)&a_src[hh * DHID + lane * 4];
    float4 d = *(const float4*)&a_dst[hh * DHID + lane * 4];
    float accs = f0.x * s.x + f0.y * s.y + f1.x * s.z + f1.y * s.w;
    float accd = f0.x * d.x + f0.y * d.y + f1.x * d.z + f1.y * d.w;
#pragma unroll
    for (int o = 16; o; o >>= 1) {
        accs += __shfl_xor_sync(0xffffffffu, accs, o);
        accd += __shfl_xor_sync(0xffffffffu, accd, o);
    }
    if (lane == 0) { as_out[gw] = accs; ad_out[gw] = accd; }
}

// ================= fused CSR softmax-aggregation (fp16 gather, warp-per-node) =================
__global__ void agg_csr_kernel(const int* __restrict__ rowptr, const int* __restrict__ rowend,
                               const int* __restrict__ colidx,
                               const __half* __restrict__ h,
                               const float* __restrict__ as_in, const float* __restrict__ ad_in,
                               float* __restrict__ out, int N)
{
    int gw = (blockIdx.x * blockDim.x + threadIdx.x) >> 5;
    int lane = threadIdx.x & 31;
    if (gw >= N) return;
    int start = rowptr[gw];
    int end   = rowend[gw];
    float2 adv = ((const float2*)ad_in)[gw];
    const uint4* h4 = (const uint4*)h;   // 8 fp16 per uint4; node stride = 32

    float acc[8];
#pragma unroll
    for (int j = 0; j < 8; j++) acc[j] = 0.f;
    float den0 = 0.f, den1 = 0.f;
    const bool head0 = lane < 16;

    for (int i = start; i < end; i++) {
        int s = __ldg(&colidx[i]);
        float2 av = ((const float2*)as_in)[s];
        float e0 = av.x + adv.x;  e0 = e0 > 0.f ? e0 : NEG_SLOPE * e0;
        float e1 = av.y + adv.y;  e1 = e1 > 0.f ? e1 : NEG_SLOPE * e1;
        float w0 = __expf(e0);
        float w1 = __expf(e1);
        den0 += w0;  den1 += w1;
        float w = head0 ? w0 : w1;
        uint4 v = h4[(size_t)s * 32 + lane];
        float2 a = __half22float2(*(const __half2*)&v.x);
        float2 b = __half22float2(*(const __half2*)&v.y);
        float2 c = __half22float2(*(const __half2*)&v.z);
        float2 d = __half22float2(*(const __half2*)&v.w);
        acc[0] = fmaf(w, a.x, acc[0]); acc[1] = fmaf(w, a.y, acc[1]);
        acc[2] = fmaf(w, b.x, acc[2]); acc[3] = fmaf(w, b.y, acc[3]);
        acc[4] = fmaf(w, c.x, acc[4]); acc[5] = fmaf(w, c.y, acc[5]);
        acc[6] = fmaf(w, d.x, acc[6]); acc[7] = fmaf(w, d.y, acc[7]);
    }
    float r = 1.f / ((head0 ? den0 : den1) + EPSV);
    float* op = out + (size_t)gw * DFEAT + lane * 8;
    *(float4*)op       = make_float4(acc[0] * r, acc[1] * r, acc[2] * r, acc[3] * r);
    *(float4*)(op + 4) = make_float4(acc[4] * r, acc[5] * r, acc[6] * r, acc[7] * r);
}

// ================= collapsed post-MLP =================
__global__ void wc_kernel(const float* __restrict__ Wp1, const float* __restrict__ bp1,
                          const float* __restrict__ Wp2, const float* __restrict__ bp2,
                          float* __restrict__ wc)
{
    int i = threadIdx.x;  // 256 threads
    float acc = 0.f;
    for (int j = 0; j < DHID; j++) acc += Wp1[i * DHID + j] * Wp2[j];
    wc[i] = acc;
    if (i == 0) {
        float b = 0.f;
        for (int j = 0; j < DHID; j++) b += bp1[j] * Wp2[j];
        wc[DFEAT] = b + bp2[0];
    }
}

__global__ void final_kernel(const float* __restrict__ agg2,
                             const float* __restrict__ b2,
                             const float* __restrict__ wc,
                             float* __restrict__ out, int N)
{
    int gw = (blockIdx.x * blockDim.x + threadIdx.x) >> 5;
    int lane = threadIdx.x & 31;
    if (gw >= N) return;
    const float* hp = agg2 + (size_t)gw * DFEAT;
    float acc = 0.f;
#pragma unroll
    for (int r = 0; r < 2; r++) {
        int cidx = r * 128 + lane * 4;
        float4 v  = *(const float4*)&hp[cidx];
        float4 bb = *(const float4*)&b2[cidx];
        float4 ww = *(const float4*)&wc[cidx];
        acc += fmaxf(v.x + bb.x, 0.f) * ww.x;
        acc += fmaxf(v.y + bb.y, 0.f) * ww.y;
        acc += fmaxf(v.z + bb.z, 0.f) * ww.z;
        acc += fmaxf(v.w + bb.w, 0.f) * ww.w;
    }
#pragma unroll
    for (int o = 16; o; o >>= 1) acc += __shfl_xor_sync(0xffffffffu, acc, o);
    if (lane == 0) {
        float z = acc + wc[DFEAT];
        out[gw] = 1.f / (1.f + expf(-z));
    }
}

// ================= launch =================
extern "C" void kernel_launch(void* const* d_in, const int* in_sizes, int n_in,
                              void* d_out, int out_size)
{
    const float* x      = (const float*)d_in[0];
    const int*   ei     = (const int*)  d_in[1];
    const float* W1     = (const float*)d_in[2];
    const float* a_src1 = (const float*)d_in[3];
    const float* a_dst1 = (const float*)d_in[4];
    const float* b1     = (const float*)d_in[5];
    const float* W2     = (const float*)d_in[6];
    const float* a_src2 = (const float*)d_in[7];
    const float* a_dst2 = (const float*)d_in[8];
    const float* b2     = (const float*)d_in[9];
    const float* Wp1    = (const float*)d_in[10];
    const float* bp1    = (const float*)d_in[11];
    const float* Wp2    = (const float*)d_in[12];
    const float* bp2    = (const float*)d_in[13];

    const int N = in_sizes[0] / 128;
    const int E = in_sizes[1] / 2;
    const int Etot = E + N;

    __half *h1, *h2;
    float *agg1, *agg2, *as, *ad, *wc;
    uint32_t *w1hi, *w1lo, *w2hi, *w2lo;
    int *cnt, *rowptr, *cursor, *colidx, *bsum;
    cudaGetSymbolAddress((void**)&h1,   g_h1);
    cudaGetSymbolAddress((void**)&agg1, g_agg1);
    cudaGetSymbolAddress((void**)&h2,   g_h2);
    cudaGetSymbolAddress((void**)&agg2, g_agg2);
    cudaGetSymbolAddress((void**)&as,   g_as);
    cudaGetSymbolAddress((void**)&ad,   g_ad);
    cudaGetSymbolAddress((void**)&wc,   g_wc);
    cudaGetSymbolAddress((void**)&w1hi, g_w1hi);
    cudaGetSymbolAddress((void**)&w1lo, g_w1lo);
    cudaGetSymbolAddress((void**)&w2hi, g_w2hi);
    cudaGetSymbolAddress((void**)&w2lo, g_w2lo);
    cudaGetSymbolAddress((void**)&cnt,    g_cnt);
    cudaGetSymbolAddress((void**)&rowptr, g_rowptr);
    cudaGetSymbolAddress((void**)&cursor, g_cursor);
    cudaGetSymbolAddress((void**)&colidx, g_colidx);
    cudaGetSymbolAddress((void**)&bsum,   g_bsum);

    const int nb = (N + 255) / 256;
    dim3 gemm_grid((N + 127) / 128, DFEAT / 64);
    const int aa_blocks    = (N * 2 * 32 + 255) / 256;
    const int agg_blocks   = (N * 32 + 255) / 256;
    const int final_blocks = (N * 32 + 255) / 256;
    const int edge_blocks  = (Etot + 255) / 256;
    const int ws1 = (DFEAT * DHID / 2 + 255) / 256;
    const int ws2 = (DFEAT * DFEAT / 2 + 255) / 256;

    // 1-3: weight splits + CSR count
    wsplit_kernel<<<ws1, 256>>>(W1, w1hi, w1lo, DHID, DFEAT);
    wsplit_kernel<<<ws2, 256>>>(W2, w2hi, w2lo, DFEAT, DFEAT);
    count_kernel<<<edge_blocks, 256>>>(ei, cnt, E, Etot);
    // 4: gemm1 (profile slot)
    gemm_f16_kernel<0><<<gemm_grid, 256>>>(x, w1hi, w1lo, nullptr, h1, N, DFEAT, DHID);
    // 5-8: finish CSR
    scan_block_sums<<<nb, 256>>>(cnt, bsum, N);
    scan_bsums<<<1, 256>>>(bsum, nb);
    scan_final<<<nb, 256>>>(cnt, bsum, rowptr, cursor, N);
    scatter_kernel<<<edge_blocks, 256>>>(ei, cursor, colidx, E, Etot);
    // 9-10: layer-1 logits + aggregation
    alpha_kernel<<<aa_blocks, 256>>>(h1, a_src1, a_dst1, as, ad, N);
    agg_csr_kernel<<<agg_blocks, 256>>>(rowptr, cursor, colidx, h1, as, ad, agg1, N);
    // 11-13: layer 2 (input = relu(agg1 + b1), fused into GEMM A-load)
    gemm_f16_kernel<1><<<gemm_grid, 256>>>(agg1, w2hi, w2lo, b1, h2, N, DFEAT, DFEAT);
    alpha_kernel<<<aa_blocks, 256>>>(h2, a_src2, a_dst2, as, ad, N);
    agg_csr_kernel<<<agg_blocks, 256>>>(rowptr, cursor, colidx, h2, as, ad, agg2, N);
    // 14-15: collapsed post-MLP + sigmoid
    wc_kernel<<<1, 256>>>(Wp1, bp1, Wp2, bp2, wc);
    final_kernel<<<final_blocks, 256>>>(agg2, b2, wc, (float*)d_out, N);
}

// round 10
// speedup vs baseline: 1.5135x; 1.0666x over previous
#include <cuda_runtime.h>
#include <cuda_fp16.h>
#include <math.h>
#include <stdint.h>

#define NNODES 50000
#define EEDGES 800000
#define ETOT   (EEDGES + NNODES)
#define DHID   128
#define DFEAT  256          // HEADS * HID
#define NEG_SLOPE 0.2f
#define EPSV 1e-16f

// ---------------- scratch (no allocation allowed; zero-initialized at load) ----------------
__device__ __half g_h1[NNODES * DFEAT];
__device__ float  g_agg1[NNODES * DFEAT];
__device__ __half g_h2[NNODES * DFEAT];
__device__ float  g_agg2[NNODES * DFEAT];
__device__ float  g_as[NNODES * 2];
__device__ float  g_ad[NNODES * 2];
__device__ float  g_wc[DFEAT + 1];
__device__ uint32_t g_w1hi[DFEAT * DHID / 2];   // W1 split, packed k-pairs [N][K/2]
__device__ uint32_t g_w1lo[DFEAT * DHID / 2];
__device__ uint32_t g_w2hi[DFEAT * DFEAT / 2];  // W2 split
__device__ uint32_t g_w2lo[DFEAT * DFEAT / 2];
__device__ int    g_cnt[NNODES];      // self-cleaning (scan_final re-zeroes)
__device__ int    g_rowptr[NNODES];
__device__ int    g_cursor[NNODES];   // after scatter: row end
__device__ int    g_colidx[ETOT];
__device__ int    g_bsum[256];

// ================= weight pre-split: W[k][n] fp32 -> hi/lo fp16 k-pairs [n][k/2] =================
__global__ void wsplit_kernel(const float* __restrict__ W,
                              uint32_t* __restrict__ hi, uint32_t* __restrict__ lo,
                              int K, int N) {
    int t = blockIdx.x * 256 + threadIdx.x;
    int total = N * (K >> 1);
    if (t >= total) return;
    int n = t / (K >> 1), k2 = t % (K >> 1);
    float x = W[(size_t)(2 * k2) * N + n];
    float y = W[(size_t)(2 * k2 + 1) * N + n];
    __half2 h = __floats2half2_rn(x, y);
    float2 hf = __half22float2(h);
    __half2 l = __floats2half2_rn(x - hf.x, y - hf.y);
    hi[t] = *(uint32_t*)&h;
    lo[t] = *(uint32_t*)&l;
}

// ================= CSR construction =================
__global__ void count_kernel(const int* __restrict__ ei, int* __restrict__ cnt,
                             int E, int Etot) {
    int t = blockIdx.x * blockDim.x + threadIdx.x;
    if (t >= Etot) return;
    int d = (t < E) ? ei[E + t] : (t - E);
    atomicAdd(&cnt[d], 1);
}

__global__ void scan_block_sums(const int* __restrict__ cnt, int* __restrict__ bsum, int N) {
    __shared__ int sh[256];
    int tid = threadIdx.x;
    int i = blockIdx.x * 256 + tid;
    sh[tid] = (i < N) ? cnt[i] : 0;
    __syncthreads();
    for (int s = 128; s > 0; s >>= 1) {
        if (tid < s) sh[tid] += sh[tid + s];
        __syncthreads();
    }
    if (tid == 0) bsum[blockIdx.x] = sh[0];
}

__global__ void scan_bsums(int* bsum, int nb) {
    __shared__ int sh[256];
    int tid = threadIdx.x;
    int v0 = (tid < nb) ? bsum[tid] : 0;
    sh[tid] = v0;
    __syncthreads();
    for (int off = 1; off < 256; off <<= 1) {
        int v = (tid >= off) ? sh[tid - off] : 0;
        __syncthreads();
        sh[tid] += v;
        __syncthreads();
    }
    if (tid < nb) bsum[tid] = sh[tid] - v0;   // exclusive
}

__global__ void scan_final(int* __restrict__ cnt, const int* __restrict__ bsum,
                           int* __restrict__ rowptr, int* __restrict__ cursor, int N) {
    __shared__ int sh[256];
    int tid = threadIdx.x;
    int i = blockIdx.x * 256 + tid;
    int v0 = (i < N) ? cnt[i] : 0;
    sh[tid] = v0;
    __syncthreads();
    for (int off = 1; off < 256; off <<= 1) {
        int v = (tid >= off) ? sh[tid - off] : 0;
        __syncthreads();
        sh[tid] += v;
        __syncthreads();
    }
    if (i < N) {
        int excl = sh[tid] - v0 + bsum[blockIdx.x];
        rowptr[i] = excl;
        cursor[i] = excl;
        cnt[i] = 0;   // self-clean for next graph replay
    }
}

__global__ void scatter_kernel(const int* __restrict__ ei, int* __restrict__ cursor,
                               int* __restrict__ colidx, int E, int Etot) {
    int t = blockIdx.x * blockDim.x + threadIdx.x;
    if (t >= Etot) return;
    int s, d;
    if (t < E) { s = ei[t]; d = ei[E + t]; } else { s = d = t - E; }
    int pos = atomicAdd(&cursor[d], 1);
    colidx[pos] = s;
}

// ================= double-fp16 tensor-core GEMM (R9-validated) =================
__device__ __forceinline__ void mma_f16(float* c, const uint32_t* a, const uint32_t* b) {
    asm volatile(
        "mma.sync.aligned.m16n8k16.row.col.f32.f16.f16.f32 "
        "{%0,%1,%2,%3}, {%4,%5,%6,%7}, {%8,%9}, {%0,%1,%2,%3};"
        : "+f"(c[0]), "+f"(c[1]), "+f"(c[2]), "+f"(c[3])
        : "r"(a[0]), "r"(a[1]), "r"(a[2]), "r"(a[3]), "r"(b[0]), "r"(b[1]));
}

template <int FUSE_RELU>
__global__ void __launch_bounds__(256) gemm_f16_kernel(
    const float* __restrict__ A,
    const uint32_t* __restrict__ Whi, const uint32_t* __restrict__ Wlo,
    const float* __restrict__ bias, __half* __restrict__ C,
    int M, int N, int K)
{
    __shared__ uint32_t Ah[128][12];   // [row][k2], pad 12: frag bank 12*gid+tig bijective
    __shared__ uint32_t Al[128][12];
    __shared__ uint32_t Bh[64][12];    // [n][k2]
    __shared__ uint32_t Bl[64][12];

    const int tid  = threadIdx.x;
    const int lane = tid & 31;
    const int warp = tid >> 5;
    const int wm   = warp & 3;     // m warp: wm*32
    const int wn   = warp >> 2;    // n warp: wn*32
    const int gid  = lane >> 2;
    const int tig  = lane & 3;
    const int m0 = blockIdx.x * 128;
    const int n0 = blockIdx.y * 64;
    const int K2 = K >> 1;

    float c_[2][4][4];
#pragma unroll
    for (int fm = 0; fm < 2; fm++)
#pragma unroll
        for (int fn = 0; fn < 4; fn++)
#pragma unroll
            for (int j = 0; j < 4; j++) c_[fm][fn][j] = 0.f;

    for (int k0 = 0; k0 < K; k0 += 16) {
        // ---- A tile (128 x 16): 512 float4, 2 per thread; split to hi/lo k-pairs ----
#pragma unroll
        for (int it = 0; it < 2; it++) {
            int idx = tid + it * 256;
            int row = idx >> 2, c4 = idx & 3;
            int gm = m0 + row;
            float4 f = make_float4(0.f, 0.f, 0.f, 0.f);
            if (gm < M) f = *(const float4*)&A[(size_t)gm * K + k0 + c4 * 4];
            if (FUSE_RELU) {
                float4 bb = *(const float4*)&bias[k0 + c4 * 4];
                f.x = fmaxf(f.x + bb.x, 0.f);
                f.y = fmaxf(f.y + bb.y, 0.f);
                f.z = fmaxf(f.z + bb.z, 0.f);
                f.w = fmaxf(f.w + bb.w, 0.f);
            }
            __half2 h01 = __floats2half2_rn(f.x, f.y);
            __half2 h23 = __floats2half2_rn(f.z, f.w);
            float2 hf01 = __half22float2(h01);
            float2 hf23 = __half22float2(h23);
            __half2 l01 = __floats2half2_rn(f.x - hf01.x, f.y - hf01.y);
            __half2 l23 = __floats2half2_rn(f.z - hf23.x, f.w - hf23.y);
            *(uint2*)&Ah[row][c4 * 2] = make_uint2(*(uint32_t*)&h01, *(uint32_t*)&h23);
            *(uint2*)&Al[row][c4 * 2] = make_uint2(*(uint32_t*)&l01, *(uint32_t*)&l23);
        }
        // ---- B tile (64 n x 8 k2): 256 uint2, 1 per thread (pre-split weights) ----
        {
            int n = tid >> 2;             // 0..63
            int kq = (tid & 3) * 2;       // 0,2,4,6
            size_t gidx = (size_t)(n0 + n) * K2 + (k0 >> 1) + kq;
            uint2 hv = *(const uint2*)&Whi[gidx];
            uint2 lv = *(const uint2*)&Wlo[gidx];
            *(uint2*)&Bh[n][kq] = hv;
            *(uint2*)&Bl[n][kq] = lv;
        }
        __syncthreads();

        uint32_t ah[2][4], al[2][4], bh[4][2], bl[4][2];
#pragma unroll
        for (int fm = 0; fm < 2; fm++) {
            int r = wm * 32 + fm * 16;
            ah[fm][0] = Ah[r + gid][tig];       al[fm][0] = Al[r + gid][tig];
            ah[fm][1] = Ah[r + gid + 8][tig];   al[fm][1] = Al[r + gid + 8][tig];
            ah[fm][2] = Ah[r + gid][tig + 4];   al[fm][2] = Al[r + gid][tig + 4];
            ah[fm][3] = Ah[r + gid + 8][tig + 4]; al[fm][3] = Al[r + gid + 8][tig + 4];
        }
#pragma unroll
        for (int fn = 0; fn < 4; fn++) {
            int cc = wn * 32 + fn * 8 + gid;
            bh[fn][0] = Bh[cc][tig];     bl[fn][0] = Bl[cc][tig];
            bh[fn][1] = Bh[cc][tig + 4]; bl[fn][1] = Bl[cc][tig + 4];
        }
#pragma unroll
        for (int fm = 0; fm < 2; fm++)
#pragma unroll
            for (int fn = 0; fn < 4; fn++) {
                mma_f16(c_[fm][fn], ah[fm], bh[fn]);   // hi*hi
                mma_f16(c_[fm][fn], ah[fm], bl[fn]);   // hi*lo
                mma_f16(c_[fm][fn], al[fm], bh[fn]);   // lo*hi
            }
        __syncthreads();
    }

    // ---- epilogue: fp16 stores ----
#pragma unroll
    for (int fm = 0; fm < 2; fm++)
#pragma unroll
        for (int fn = 0; fn < 4; fn++) {
            int gm = m0 + wm * 32 + fm * 16 + gid;
            int gn = n0 + wn * 32 + fn * 8 + 2 * tig;
            if (gm < M)
                *(__half2*)&C[(size_t)gm * N + gn] =
                    __floats2half2_rn(c_[fm][fn][0], c_[fm][fn][1]);
            if (gm + 8 < M)
                *(__half2*)&C[(size_t)(gm + 8) * N + gn] =
                    __floats2half2_rn(c_[fm][fn][2], c_[fm][fn][3]);
        }
}

// ================= attention logits (fp16 h) =================
__global__ void alpha_kernel(const __half* __restrict__ h,
                             const float* __restrict__ a_src,
                             const float* __restrict__ a_dst,
                             float* __restrict__ as_out, float* __restrict__ ad_out,
                             int N)
{
    int gw = (blockIdx.x * blockDim.x + threadIdx.x) >> 5;
    int lane = threadIdx.x & 31;
    if (gw >= N * 2) return;
    int n = gw >> 1, hh = gw & 1;
    const __half2* hp = (const __half2*)(h + (size_t)n * DFEAT + hh * DHID);
    __half2 p0 = hp[lane * 2], p1 = hp[lane * 2 + 1];
    float2 f0 = __half22float2(p0), f1 = __half22float2(p1);
    float4 s = *(const float4*)&a_src[hh * DHID + lane * 4];
    float4 d = *(const float4*)&a_dst[hh * DHID + lane * 4];
    float accs = f0.x * s.x + f0.y * s.y + f1.x * s.z + f1.y * s.w;
    float accd = f0.x * d.x + f0.y * d.y + f1.x * d.z + f1.y * d.w;
#pragma unroll
    for (int o = 16; o; o >>= 1) {
        accs += __shfl_xor_sync(0xffffffffu, accs, o);
        accd += __shfl_xor_sync(0xffffffffu, accd, o);
    }
    if (lane == 0) { as_out[gw] = accs; ad_out[gw] = accd; }
}

// ================= fused CSR softmax-aggregation (fp16 gather, software-pipelined) =================
__global__ void agg_csr_kernel(const int* __restrict__ rowptr, const int* __restrict__ rowend,
                               const int* __restrict__ colidx,
                               const __half* __restrict__ h,
                               const float* __restrict__ as_in, const float* __restrict__ ad_in,
                               float* __restrict__ out, int N)
{
    int gw = (blockIdx.x * blockDim.x + threadIdx.x) >> 5;
    int lane = threadIdx.x & 31;
    if (gw >= N) return;
    int start = rowptr[gw];
    int end   = rowend[gw];
    float2 adv = ((const float2*)ad_in)[gw];
    const uint4* h4 = (const uint4*)h;   // 8 fp16 per uint4; node stride = 32

    float acc[8];
#pragma unroll
    for (int j = 0; j < 8; j++) acc[j] = 0.f;
    float den0 = 0.f, den1 = 0.f;
    const bool head0 = lane < 16;

    // prologue: prefetch edge 0 (deg >= 1 always due to self loop)
    int s = __ldg(&colidx[start]);
    float2 av = ((const float2*)as_in)[s];
    uint4 v = h4[(size_t)s * 32 + lane];

    for (int i = start; i < end; i++) {
        float2 av_c = av;
        uint4 v_c = v;
        if (i + 1 < end) {                      // prefetch next edge while computing current
            int s2 = __ldg(&colidx[i + 1]);
            av = ((const float2*)as_in)[s2];
            v = h4[(size_t)s2 * 32 + lane];
        }
        float e0 = av_c.x + adv.x;  e0 = e0 > 0.f ? e0 : NEG_SLOPE * e0;
        float e1 = av_c.y + adv.y;  e1 = e1 > 0.f ? e1 : NEG_SLOPE * e1;
        float w0 = __expf(e0);
        float w1 = __expf(e1);
        den0 += w0;  den1 += w1;
        float w = head0 ? w0 : w1;
        float2 a = __half22float2(*(const __half2*)&v_c.x);
        float2 b = __half22float2(*(const __half2*)&v_c.y);
        float2 c = __half22float2(*(const __half2*)&v_c.z);
        float2 d = __half22float2(*(const __half2*)&v_c.w);
        acc[0] = fmaf(w, a.x, acc[0]); acc[1] = fmaf(w, a.y, acc[1]);
        acc[2] = fmaf(w, b.x, acc[2]); acc[3] = fmaf(w, b.y, acc[3]);
        acc[4] = fmaf(w, c.x, acc[4]); acc[5] = fmaf(w, c.y, acc[5]);
        acc[6] = fmaf(w, d.x, acc[6]); acc[7] = fmaf(w, d.y, acc[7]);
    }
    float r = 1.f / ((head0 ? den0 : den1) + EPSV);
    float* op = out + (size_t)gw * DFEAT + lane * 8;
    *(float4*)op       = make_float4(acc[0] * r, acc[1] * r, acc[2] * r, acc[3] * r);
    *(float4*)(op + 4) = make_float4(acc[4] * r, acc[5] * r, acc[6] * r, acc[7] * r);
}

// ================= collapsed post-MLP =================
__global__ void wc_kernel(const float* __restrict__ Wp1, const float* __restrict__ bp1,
                          const float* __restrict__ Wp2, const float* __restrict__ bp2,
                          float* __restrict__ wc)
{
    int i = threadIdx.x;  // 256 threads
    float acc = 0.f;
    for (int j = 0; j < DHID; j++) acc += Wp1[i * DHID + j] * Wp2[j];
    wc[i] = acc;
    if (i == 0) {
        float b = 0.f;
        for (int j = 0; j < DHID; j++) b += bp1[j] * Wp2[j];
        wc[DFEAT] = b + bp2[0];
    }
}

__global__ void final_kernel(const float* __restrict__ agg2,
                             const float* __restrict__ b2,
                             const float* __restrict__ wc,
                             float* __restrict__ out, int N)
{
    int gw = (blockIdx.x * blockDim.x + threadIdx.x) >> 5;
    int lane = threadIdx.x & 31;
    if (gw >= N) return;
    const float* hp = agg2 + (size_t)gw * DFEAT;
    float acc = 0.f;
#pragma unroll
    for (int r = 0; r < 2; r++) {
        int cidx = r * 128 + lane * 4;
        float4 v  = *(const float4*)&hp[cidx];
        float4 bb = *(const float4*)&b2[cidx];
        float4 ww = *(const float4*)&wc[cidx];
        acc += fmaxf(v.x + bb.x, 0.f) * ww.x;
        acc += fmaxf(v.y + bb.y, 0.f) * ww.y;
        acc += fmaxf(v.z + bb.z, 0.f) * ww.z;
        acc += fmaxf(v.w + bb.w, 0.f) * ww.w;
    }
#pragma unroll
    for (int o = 16; o; o >>= 1) acc += __shfl_xor_sync(0xffffffffu, acc, o);
    if (lane == 0) {
        float z = acc + wc[DFEAT];
        out[gw] = 1.f / (1.f + expf(-z));
    }
}

// ================= launch (fork-join: CSR/wsplit2/wc overlap gemm1 chain) =================
extern "C" void kernel_launch(void* const* d_in, const int* in_sizes, int n_in,
                              void* d_out, int out_size)
{
    const float* x      = (const float*)d_in[0];
    const int*   ei     = (const int*)  d_in[1];
    const float* W1     = (const float*)d_in[2];
    const float* a_src1 = (const float*)d_in[3];
    const float* a_dst1 = (const float*)d_in[4];
    const float* b1     = (const float*)d_in[5];
    const float* W2     = (const float*)d_in[6];
    const float* a_src2 = (const float*)d_in[7];
    const float* a_dst2 = (const float*)d_in[8];
    const float* b2     = (const float*)d_in[9];
    const float* Wp1    = (const float*)d_in[10];
    const float* bp1    = (const float*)d_in[11];
    const float* Wp2    = (const float*)d_in[12];
    const float* bp2    = (const float*)d_in[13];

    const int N = in_sizes[0] / 128;
    const int E = in_sizes[1] / 2;
    const int Etot = E + N;

    __half *h1, *h2;
    float *agg1, *agg2, *as, *ad, *wc;
    uint32_t *w1hi, *w1lo, *w2hi, *w2lo;
    int *cnt, *rowptr, *cursor, *colidx, *bsum;
    cudaGetSymbolAddress((void**)&h1,   g_h1);
    cudaGetSymbolAddress((void**)&agg1, g_agg1);
    cudaGetSymbolAddress((void**)&h2,   g_h2);
    cudaGetSymbolAddress((void**)&agg2, g_agg2);
    cudaGetSymbolAddress((void**)&as,   g_as);
    cudaGetSymbolAddress((void**)&ad,   g_ad);
    cudaGetSymbolAddress((void**)&wc,   g_wc);
    cudaGetSymbolAddress((void**)&w1hi, g_w1hi);
    cudaGetSymbolAddress((void**)&w1lo, g_w1lo);
    cudaGetSymbolAddress((void**)&w2hi, g_w2hi);
    cudaGetSymbolAddress((void**)&w2lo, g_w2lo);
    cudaGetSymbolAddress((void**)&cnt,    g_cnt);
    cudaGetSymbolAddress((void**)&rowptr, g_rowptr);
    cudaGetSymbolAddress((void**)&cursor, g_cursor);
    cudaGetSymbolAddress((void**)&colidx, g_colidx);
    cudaGetSymbolAddress((void**)&bsum,   g_bsum);

    const int nb = (N + 255) / 256;
    dim3 gemm_grid((N + 127) / 128, DFEAT / 64);
    const int aa_blocks    = (N * 2 * 32 + 255) / 256;
    const int agg_blocks   = (N * 32 + 255) / 256;
    const int final_blocks = (N * 32 + 255) / 256;
    const int edge_blocks  = (Etot + 255) / 256;
    const int ws1 = (DFEAT * DHID / 2 + 255) / 256;
    const int ws2 = (DFEAT * DFEAT / 2 + 255) / 256;

    // side stream + events, created per call (host-side only; not captured as graph
    // nodes; intentionally not destroyed — destroying capture-referenced objects
    // during an active capture is invalid, and kernel_launch is called O(1) times).
    cudaStream_t s1;
    cudaStreamCreateWithFlags(&s1, cudaStreamNonBlocking);
    cudaEvent_t evRoot, evCsr, evW2, evWc;
    cudaEventCreateWithFlags(&evRoot, cudaEventDisableTiming);
    cudaEventCreateWithFlags(&evCsr,  cudaEventDisableTiming);
    cudaEventCreateWithFlags(&evW2,   cudaEventDisableTiming);
    cudaEventCreateWithFlags(&evWc,   cudaEventDisableTiming);

    // fork side stream off the (captured) default stream
    cudaEventRecord(evRoot, 0);
    cudaStreamWaitEvent(s1, evRoot, 0);

    // launch order keeps gemm1 as the 4th kernel (ncu profile slot)
    wsplit_kernel<<<ws1, 256>>>(W1, w1hi, w1lo, DHID, DFEAT);                       // 1 (s0)
    count_kernel<<<edge_blocks, 256, 0, s1>>>(ei, cnt, E, Etot);                    // 2 (s1)
    wsplit_kernel<<<ws2, 256, 0, s1>>>(W2, w2hi, w2lo, DFEAT, DFEAT);               // 3 (s1)
    gemm_f16_kernel<0><<<gemm_grid, 256>>>(x, w1hi, w1lo, nullptr, h1, N, DFEAT, DHID); // 4 (s0)
    cudaEventRecord(evW2, s1);
    scan_block_sums<<<nb, 256, 0, s1>>>(cnt, bsum, N);                              // 5 (s1)
    scan_bsums<<<1, 256, 0, s1>>>(bsum, nb);                                        // 6 (s1)
    scan_final<<<nb, 256, 0, s1>>>(cnt, bsum, rowptr, cursor, N);                   // 7 (s1)
    scatter_kernel<<<edge_blocks, 256, 0, s1>>>(ei, cursor, colidx, E, Etot);       // 8 (s1)
    cudaEventRecord(evCsr, s1);
    wc_kernel<<<1, 256, 0, s1>>>(Wp1, bp1, Wp2, bp2, wc);                           // 9 (s1)
    cudaEventRecord(evWc, s1);

    // main chain on s0
    alpha_kernel<<<aa_blocks, 256>>>(h1, a_src1, a_dst1, as, ad, N);                // 10
    cudaStreamWaitEvent(0, evCsr, 0);
    agg_csr_kernel<<<agg_blocks, 256>>>(rowptr, cursor, colidx, h1, as, ad, agg1, N); // 11
    cudaStreamWaitEvent(0, evW2, 0);
    gemm_f16_kernel<1><<<gemm_grid, 256>>>(agg1, w2hi, w2lo, b1, h2, N, DFEAT, DFEAT); // 12
    alpha_kernel<<<aa_blocks, 256>>>(h2, a_src2, a_dst2, as, ad, N);                // 13
    agg_csr_kernel<<<agg_blocks, 256>>>(rowptr, cursor, colidx, h2, as, ad, agg2, N); // 14
    cudaStreamWaitEvent(0, evWc, 0);
    final_kernel<<<final_blocks, 256>>>(agg2, b2, wc, (float*)d_out, N);            // 15
}